// round 5
// baseline (speedup 1.0000x reference)
#include <cuda_runtime.h>

// B, N, D, L = 32, 1000, 256, 3
#define BB 32
#define NN 1000
#define DD 256
#define LL 3
#define TOTAL4 (BB * NN * DD / 4) // 2,048,000 float4s per output half

// Scratch (no device allocation allowed -> __device__ global)
__device__ float g_v[BB * DD];

// ---------------------------------------------------------------------------
// KA: fused mean-reduce + 3-layer GEMV chain. One CTA per batch element.
// Block (64,16) = 1024 threads. Thread (x,y): float4-column x, row-group y.
// Each thread sums rows y, y+16, ..., with 8-deep front-batched LDG.128.
// Then smem reduce, then GEMV with K split 4 ways across thread groups.
// ---------------------------------------------------------------------------
__global__ __launch_bounds__(1024, 1)
void k_head(const float* __restrict__ nf,
            const float* __restrict__ Ws,
            const float* __restrict__ bs) {
    const int b = blockIdx.x;
    const int x = threadIdx.x;   // 0..63
    const int y = threadIdx.y;   // 0..15
    const int tid = y * 64 + x;

    const float4* __restrict__ nf4 =
        reinterpret_cast<const float4*>(nf) + (size_t)b * NN * 64;

    const float4 z4 = make_float4(0.f, 0.f, 0.f, 0.f);
    float4 s0 = z4, s1 = z4;

    // rows r = y + 16*i, i in [0,63); guard r < 1000
#pragma unroll
    for (int j = 0; j < 8; j++) {
        float4 a[8];
#pragma unroll
        for (int k = 0; k < 8; k++) {
            const int i = j * 8 + k;
            const int r = y + 16 * i;
            a[k] = (i < 63 && r < NN) ? nf4[r * 64 + x] : z4;
        }
#pragma unroll
        for (int k = 0; k < 8; k += 2) {
            s0.x += a[k].x; s0.y += a[k].y; s0.z += a[k].z; s0.w += a[k].w;
            s1.x += a[k+1].x; s1.y += a[k+1].y; s1.z += a[k+1].z; s1.w += a[k+1].w;
        }
    }
    float4 s = make_float4(s0.x + s1.x, s0.y + s1.y, s0.z + s1.z, s0.w + s1.w);

    // cross-warp reduction over the 16 row-groups
    __shared__ float4 sm[16][64];
    sm[y][x] = s;
    __syncthreads();
    if (y < 8) {
        float4 t = sm[y][x], u = sm[y + 8][x];
        t.x += u.x; t.y += u.y; t.z += u.z; t.w += u.w;
        sm[y][x] = t;
    }
    __syncthreads();
    if (y < 4) {
        float4 t = sm[y][x], u = sm[y + 4][x];
        t.x += u.x; t.y += u.y; t.z += u.z; t.w += u.w;
        sm[y][x] = t;
    }
    __syncthreads();

    __shared__ float sv[DD];
    __shared__ float part[4][DD];
    if (y == 0) {
        float4 t = sm[0][x];
        const float4 t1 = sm[1][x], t2 = sm[2][x], t3 = sm[3][x];
        t.x += t1.x + t2.x + t3.x;
        t.y += t1.y + t2.y + t3.y;
        t.z += t1.z + t2.z + t3.z;
        t.w += t1.w + t2.w + t3.w;
        const float inv = 1.0f / (float)NN;
        sv[4 * x + 0] = t.x * inv;
        sv[4 * x + 1] = t.y * inv;
        sv[4 * x + 2] = t.z * inv;
        sv[4 * x + 3] = t.w * inv;
    }
    __syncthreads();

    // 3 fused 256x256 GEMVs: out-column o = tid&255, K-group g = tid>>8
    const int o = tid & (DD - 1);
    const int g = tid >> 8;     // 0..3
#pragma unroll
    for (int l = 0; l < LL; l++) {
        const float* __restrict__ W = Ws + l * DD * DD;
        float acc = 0.f;
        const int k0 = g * 64;
#pragma unroll 8
        for (int k = k0; k < k0 + 64; k++)
            acc = fmaf(sv[k], W[k * DD + o], acc);   // coalesced, L2-resident
        part[g][o] = acc;
        __syncthreads();
        if (g == 0) {
            float r = part[0][o] + part[1][o] + part[2][o] + part[3][o] + bs[l * DD + o];
            sv[o] = (l < LL - 1) ? fmaxf(r, 0.f) : r;
        }
        __syncthreads();
    }
    if (g == 0) g_v[b * DD + o] = sv[o];
}

// ---------------------------------------------------------------------------
// KB: out[0:BND]     = node_feature + v[b,:]  (nf L2-hot from KA's read)
//     out[BND:2BND]  = node_feature (copy)
// 4 front-batched float4 loads per thread, streaming stores.
// ---------------------------------------------------------------------------
__global__ void k_out(const float* __restrict__ nf, float* __restrict__ out) {
    const int stride = gridDim.x * blockDim.x;           // 512,000
    const int i0 = blockIdx.x * blockDim.x + threadIdx.x;

    const float4* __restrict__ nf4 = reinterpret_cast<const float4*>(nf);
    float4* o4 = reinterpret_cast<float4*>(out);

    const int ia = i0, ib = i0 + stride, ic = i0 + 2 * stride, id = i0 + 3 * stride;

    const float4 a0 = nf4[ia];
    const float4 a1 = nf4[ib];
    const float4 a2 = nf4[ic];
    const float4 a3 = nf4[id];

#define DO_ONE(idx, a)                                                        \
    {                                                                         \
        const int i = (idx) << 2;                                             \
        const int bb = i / (NN * DD);                                         \
        const int dd = i & (DD - 1);                                          \
        const float4 v = *reinterpret_cast<const float4*>(g_v + bb * DD + dd);\
        float4 r;                                                             \
        r.x = (a).x + v.x; r.y = (a).y + v.y;                                 \
        r.z = (a).z + v.z; r.w = (a).w + v.w;                                 \
        __stcs(o4 + (idx), r);                                                \
        __stcs(o4 + TOTAL4 + (idx), (a));                                     \
    }

    DO_ONE(ia, a0)
    DO_ONE(ib, a1)
    DO_ONE(ic, a2)
    DO_ONE(id, a3)
#undef DO_ONE
}

extern "C" void kernel_launch(void* const* d_in, const int* in_sizes, int n_in,
                              void* d_out, int out_size) {
    // Inputs in metadata order: x (unused), node_feature, Ws, bs
    const float* nf = (const float*)d_in[1];
    const float* Ws = (const float*)d_in[2];
    const float* bs = (const float*)d_in[3];
    float* out = (float*)d_out;

    dim3 bA(64, 16);
    k_head<<<BB, bA>>>(nf, Ws, bs);

    // 2000 blocks * 256 threads * 4 float4/thread = 2,048,000 = TOTAL4 exactly
    k_out<<<2000, 256>>>(nf, out);
}